// round 14
// baseline (speedup 1.0000x reference)
#include <cuda_runtime.h>
#include <cuda_fp16.h>
#include <stdint.h>

#define M_ROWS 8192
#define N_CODES 8192
#define K_DIM 256

#define BM 128
#define BN 128
#define NCTA_N (N_CODES / BN)        // 64
#define KC 128                       // int8 K elems per chunk (128 B rows)
#define NCHUNK (K_DIM / KC)          // 2
#define TILE_BYTES (128 * 128)       // 128 rows x 128 bytes
#define SMEM_DYN (4 * TILE_BYTES)    // 2 stages x (A + B) = 64 KB
#define MARGIN 6.0f                  // ~8 sigma of int8 screen error difference

typedef unsigned long long u64;

__device__ float g_esq[N_CODES];
__device__ float g_sx[M_ROWS];                 // per-row quant scale for x
__device__ float g_se[N_CODES];                // per-row quant scale for embed
__device__ u64 g_cand[M_ROWS][NCTA_N][2];      // top-2 approx candidates per (row, N-CTA)
__device__ signed char g_xq[M_ROWS * K_DIM];
__device__ signed char g_eq[N_CODES * K_DIM];

// ---------------- baseline-PTX helpers (valid on plain sm_103 target) ----------------

__device__ __forceinline__ uint32_t smem_u32(const void* p) {
    uint32_t a;
    asm("{ .reg .u64 t; cvta.to.shared.u64 t, %1; cvt.u32.u64 %0, t; }" : "=r"(a) : "l"(p));
    return a;
}

__device__ __forceinline__ void cp16(uint32_t dst, const void* src) {
    asm volatile("cp.async.cg.shared.global [%0], [%1], 16;" :: "r"(dst), "l"(src));
}
__device__ __forceinline__ void cp_commit() { asm volatile("cp.async.commit_group;" ::: "memory"); }
template <int N> __device__ __forceinline__ void cp_wait() {
    asm volatile("cp.async.wait_group %0;" :: "n"(N) : "memory");
}

__device__ __forceinline__ void ldsm4(uint32_t& r0, uint32_t& r1, uint32_t& r2, uint32_t& r3,
                                      uint32_t addr) {
    asm volatile("ldmatrix.sync.aligned.m8n8.x4.shared.b16 {%0,%1,%2,%3}, [%4];"
                 : "=r"(r0), "=r"(r1), "=r"(r2), "=r"(r3) : "r"(addr));
}

// s8 MMA: m16n8k32, s32 accumulate. Fragment byte-layout identical to f16 m16n8k16.
__device__ __forceinline__ void mma_s8(int* d, const uint32_t* a, uint32_t b0, uint32_t b1) {
    asm volatile(
        "mma.sync.aligned.m16n8k32.row.col.s32.s8.s8.s32 "
        "{%0,%1,%2,%3}, {%4,%5,%6,%7}, {%8,%9}, {%0,%1,%2,%3};"
        : "+r"(d[0]), "+r"(d[1]), "+r"(d[2]), "+r"(d[3])
        : "r"(a[0]), "r"(a[1]), "r"(a[2]), "r"(a[3]), "r"(b0), "r"(b1));
}

__device__ __forceinline__ u64 pack_key(float v, unsigned int idx) {
    unsigned int u = __float_as_uint(v);
    u = (u & 0x80000000u) ? ~u : (u | 0x80000000u);
    return ((u64)u << 32) | (u64)idx;
}
__device__ __forceinline__ float unpack_val(u64 k) {
    unsigned int u = (unsigned int)(k >> 32);
    u = (u & 0x80000000u) ? (u & 0x7FFFFFFFu) : ~u;
    return __uint_as_float(u);
}

__device__ __forceinline__ u64 u64min(u64 a, u64 b) { return a < b ? a : b; }
__device__ __forceinline__ u64 u64max(u64 a, u64 b) { return a > b ? a : b; }

__device__ __forceinline__ void top2_merge(u64& k1, u64& k2, u64 j1, u64 j2) {
    u64 lo = u64min(k1, j1);
    u64 hi = u64max(k1, j1);
    k1 = lo;
    k2 = u64min(u64min(k2, j2), hi);
}

__device__ __forceinline__ void top2f_push(float& v1, unsigned& i1, float& v2, unsigned& i2,
                                           float d, unsigned n) {
    if (d < v1) { v2 = v1; i2 = i1; v1 = d; i1 = n; }
    else if (d < v2) { v2 = d; i2 = n; }
}

// ---------------- Prologue (fused): int8 quant of x and embed + scales + e_sq ----------------
// One warp per row; lanes cover 8 contiguous floats each.

__global__ __launch_bounds__(256) void vq_prep_kernel(const float* __restrict__ x,
                                                      const float* __restrict__ embed) {
    const int row = blockIdx.x * 8 + (threadIdx.x >> 5);
    const int lane = threadIdx.x & 31;
    const bool is_x = row < M_ROWS;
    const int r = is_x ? row : row - M_ROWS;
    const float* src = is_x ? (x + (size_t)r * K_DIM) : (embed + (size_t)r * K_DIM);
    signed char* dst = is_x ? (g_xq + (size_t)r * K_DIM) : (g_eq + (size_t)r * K_DIM);

    const float4 v0 = __ldg((const float4*)src + lane * 2);
    const float4 v1 = __ldg((const float4*)src + lane * 2 + 1);
    float f[8] = {v0.x, v0.y, v0.z, v0.w, v1.x, v1.y, v1.z, v1.w};

    float mx = 0.f, s = 0.f;
    #pragma unroll
    for (int i = 0; i < 8; i++) {
        mx = fmaxf(mx, fabsf(f[i]));
        s = fmaf(f[i], f[i], s);
    }
    #pragma unroll
    for (int o = 16; o > 0; o >>= 1) {
        mx = fmaxf(mx, __shfl_xor_sync(0xffffffffu, mx, o));
        s += __shfl_xor_sync(0xffffffffu, s, o);
    }
    mx = fmaxf(mx, 1e-30f);
    const float inv = 127.f / mx;

    signed char q[8];
    #pragma unroll
    for (int i = 0; i < 8; i++) {
        float t = fminf(fmaxf(f[i] * inv, -127.f), 127.f);
        q[i] = (signed char)__float2int_rn(t);
    }
    *((uint2*)(dst + lane * 8)) = *(const uint2*)q;

    if (lane == 0) {
        const float sc = mx * (1.f / 127.f);
        if (is_x) g_sx[r] = sc;
        else { g_se[r] = sc; g_esq[r] = s; }
    }
}

// ---------------- Phase 1: int8 screening GEMM (128x128) + per-CTA top-2 ----------------

__global__ __launch_bounds__(256, 2) void vq_mma_kernel() {
    extern __shared__ char tiles[];
    __shared__ float esq_s[BN];
    __shared__ float se_s[BN];
    __shared__ float sx_s[BM];
    __shared__ u64 red[2][BM][2];

    const int tid = threadIdx.x;
    const int wid = tid >> 5;
    const int lane = tid & 31;
    const int m0 = blockIdx.x * BM;
    const int n0 = blockIdx.y * BN;
    const int wm0 = (wid & 3) * 32;        // warp M origin (4 warps in M)
    const int wn0 = (wid >> 2) * 64;       // warp N origin (2 warps in N)

    if (tid < BN) {
        esq_s[tid] = g_esq[n0 + tid];
        se_s[tid] = g_se[n0 + tid];
    }
    if (tid < BM) sx_s[tid] = g_sx[m0 + tid];

    const uint32_t tiles_base = smem_u32(tiles);

    // tile fill mapping: row = tid>>1 (0..127), 64-byte half = tid&1, SW128 swizzle
    const int lrow = tid >> 1;
    const int lhalf = tid & 1;
    uint32_t st_off[4];
    {
        const uint32_t off0 = (uint32_t)lrow * 128u + (uint32_t)lhalf * 64u;
        #pragma unroll
        for (int i = 0; i < 4; i++) {
            uint32_t o = off0 + i * 16u;
            st_off[i] = o ^ ((o >> 3) & 0x70u);
        }
    }
    // int8 rows: K_DIM bytes per row; each thread copies 64 bytes per tile
    const size_t a_off = (size_t)(m0 + lrow) * K_DIM + lhalf * 64;
    const size_t b_off = (size_t)(n0 + lrow) * K_DIM + lhalf * 64;

    // ldmatrix addressing (byte-identical to the f16 layout)
    const int l15 = lane & 15;
    const int hi16 = (lane >> 4) * 16;
    uint32_t arow[2], arx[2], brow[4], brx[4];
    #pragma unroll
    for (int mi = 0; mi < 2; mi++) {
        int r = wm0 + mi * 16 + l15;
        arow[mi] = (uint32_t)r * 128u;
        arx[mi] = (uint32_t)(r & 7) * 16u;
    }
    #pragma unroll
    for (int g = 0; g < 4; g++) {
        int r = wn0 + g * 16 + l15;
        brow[g] = (uint32_t)r * 128u;
        brx[g] = (uint32_t)(r & 7) * 16u;
    }

    int acc[2][8][4];
    #pragma unroll
    for (int mi = 0; mi < 2; mi++)
        #pragma unroll
        for (int nj = 0; nj < 8; nj++)
            #pragma unroll
            for (int q = 0; q < 4; q++) acc[mi][nj][q] = 0;

    // issue both chunks' copies (stages 0, 1)
    #pragma unroll
    for (int c0 = 0; c0 < NCHUNK; c0++) {
        uint32_t ta = tiles_base + (c0 * 2) * TILE_BYTES;
        uint32_t tb = ta + TILE_BYTES;
        const int kofs = c0 * KC;
        #pragma unroll
        for (int i = 0; i < 4; i++) {
            cp16(ta + st_off[i], &g_xq[a_off + kofs] + i * 16);
            cp16(tb + st_off[i], &g_eq[b_off + kofs] + i * 16);
        }
        cp_commit();
    }

    #pragma unroll
    for (int c = 0; c < NCHUNK; c++) {
        if (c + 1 < NCHUNK) cp_wait<1>(); else cp_wait<0>();
        __syncthreads();

        const uint32_t ta = tiles_base + (c * 2) * TILE_BYTES;
        const uint32_t tb = ta + TILE_BYTES;
        #pragma unroll
        for (int ks = 0; ks < 4; ks++) {            // 32 bytes of K per step
            const uint32_t kc = (uint32_t)(ks * 32 + hi16);
            uint32_t a[2][4], b[4][4];
            #pragma unroll
            for (int mi = 0; mi < 2; mi++)
                ldsm4(a[mi][0], a[mi][1], a[mi][2], a[mi][3],
                      ta + arow[mi] + (kc ^ arx[mi]));
            #pragma unroll
            for (int g = 0; g < 4; g++)
                ldsm4(b[g][0], b[g][1], b[g][2], b[g][3],
                      tb + brow[g] + (kc ^ brx[g]));
            #pragma unroll
            for (int mi = 0; mi < 2; mi++)
                #pragma unroll
                for (int g = 0; g < 4; g++) {
                    mma_s8(acc[mi][g * 2 + 0], a[mi], b[g][0], b[g][2]);
                    mma_s8(acc[mi][g * 2 + 1], a[mi], b[g][1], b[g][3]);
                }
        }
        __syncthreads();
    }

    // ---- epilogue: approx dist = e_sq[n] - 2*sx*se[n]*idot; fp32 top-2 per (row, CTA) ----
    const int cbase = wn0 + (lane & 3) * 2;
    #pragma unroll
    for (int mi = 0; mi < 2; mi++) {
        #pragma unroll
        for (int rh = 0; rh < 2; rh++) {
            const int row = wm0 + mi * 16 + rh * 8 + (lane >> 2);
            const float sx2 = 2.f * sx_s[row];
            float v1 = 3.4e38f, v2 = 3.4e38f;
            unsigned i1 = 0, i2 = 0;
            #pragma unroll
            for (int nj = 0; nj < 8; nj++) {
                const int nc = cbase + nj * 8;
                const float t0 = se_s[nc] * (float)acc[mi][nj][rh * 2 + 0];
                const float t1 = se_s[nc + 1] * (float)acc[mi][nj][rh * 2 + 1];
                const float d0 = fmaf(-sx2, t0, esq_s[nc]);
                const float d1 = fmaf(-sx2, t1, esq_s[nc + 1]);
                top2f_push(v1, i1, v2, i2, d0, (unsigned)(n0 + nc));
                top2f_push(v1, i1, v2, i2, d1, (unsigned)(n0 + nc + 1));
            }
            u64 k1 = pack_key(v1, i1), k2 = pack_key(v2, i2);
            #pragma unroll
            for (int o = 1; o <= 2; o <<= 1) {
                u64 j1 = __shfl_xor_sync(0xffffffffu, k1, o);
                u64 j2 = __shfl_xor_sync(0xffffffffu, k2, o);
                top2_merge(k1, k2, j1, j2);
            }
            if ((lane & 3) == 0) {
                red[wid >> 2][row][0] = k1;
                red[wid >> 2][row][1] = k2;
            }
        }
    }
    __syncthreads();
    if (tid < BM) {
        u64 k1 = red[0][tid][0], k2 = red[0][tid][1];
        top2_merge(k1, k2, red[1][tid][0], red[1][tid][1]);
        g_cand[m0 + tid][blockIdx.y][0] = k1;
        g_cand[m0 + tid][blockIdx.y][1] = k2;
    }
}

// ---------------- Phase 2: exact fp32 rescue + output write (one warp per row) ----------------

__global__ __launch_bounds__(256) void vq_refine_kernel(const float* __restrict__ x,
                                                        const float* __restrict__ embed,
                                                        float* __restrict__ out,
                                                        int write_idx) {
    const int row = blockIdx.x * 8 + (threadIdx.x >> 5);
    const int lane = threadIdx.x & 31;

    const float4* xr = (const float4*)(x + (size_t)row * K_DIM);
    const float4 xa = __ldg(&xr[lane * 2]);
    const float4 xb = __ldg(&xr[lane * 2 + 1]);

    // this row's 128 candidate keys (4 per lane)
    const u64* cp = &g_cand[row][0][0];
    u64 keys[4];
    #pragma unroll
    for (int i = 0; i < 4; i++) keys[i] = cp[lane + 32 * i];

    u64 kmin = u64min(u64min(keys[0], keys[1]), u64min(keys[2], keys[3]));
    #pragma unroll
    for (int o = 16; o > 0; o >>= 1)
        kmin = u64min(kmin, __shfl_xor_sync(0xffffffffu, kmin, o));
    const float thresh = unpack_val(kmin) + MARGIN;

    u64 best = 0xFFFFFFFFFFFFFFFFull;
    #pragma unroll
    for (int i = 0; i < 4; i++) {
        unsigned mask = __ballot_sync(0xffffffffu, unpack_val(keys[i]) <= thresh);
        while (mask) {
            const int src = __ffs(mask) - 1;
            mask &= mask - 1;
            const unsigned idx = (unsigned)(__shfl_sync(0xffffffffu, keys[i], src) & 0xFFFFFFFFull);
            const float4* er = (const float4*)(embed + (size_t)idx * K_DIM);
            const float4 ea = __ldg(&er[lane * 2]);
            const float4 eb = __ldg(&er[lane * 2 + 1]);
            float s = xa.x * ea.x + xa.y * ea.y + xa.z * ea.z + xa.w * ea.w
                    + xb.x * eb.x + xb.y * eb.y + xb.z * eb.z + xb.w * eb.w;
            #pragma unroll
            for (int o = 16; o > 0; o >>= 1) s += __shfl_xor_sync(0xffffffffu, s, o);
            const float d = fmaf(-2.f, s, __ldg(&g_esq[idx]));
            best = u64min(best, pack_key(d, idx));
        }
    }

    // winner: gather codebook row directly into the output
    const unsigned widx = (unsigned)(__shfl_sync(0xffffffffu, best, 0) & 0xFFFFFFFFull);
    const float4* er = (const float4*)(embed + (size_t)widx * K_DIM);
    float4* orow = (float4*)(out + (size_t)row * K_DIM);
    orow[lane * 2] = __ldg(&er[lane * 2]);
    orow[lane * 2 + 1] = __ldg(&er[lane * 2 + 1]);
    if (write_idx && lane == 0)
        out[(size_t)M_ROWS * K_DIM + row] = (float)widx;
}

extern "C" void kernel_launch(void* const* d_in, const int* in_sizes, int n_in,
                              void* d_out, int out_size) {
    const float* x = (const float*)d_in[0];      // [8,1024,256] f32
    const float* embed = (const float*)d_in[1];  // [8192,256] f32
    float* out = (float*)d_out;

    cudaFuncSetAttribute(vq_mma_kernel, cudaFuncAttributeMaxDynamicSharedMemorySize, SMEM_DYN);

    vq_prep_kernel<<<(M_ROWS + N_CODES) / 8, 256>>>(x, embed);

    dim3 grid(M_ROWS / BM, N_CODES / BN);
    vq_mma_kernel<<<grid, 256, SMEM_DYN>>>();

    const int write_idx = (out_size >= M_ROWS * K_DIM + M_ROWS) ? 1 : 0;
    vq_refine_kernel<<<M_ROWS / 8, 256>>>(x, embed, out, write_idx);
}